// round 8
// baseline (speedup 1.0000x reference)
#include <cuda_runtime.h>
#include <cstdint>

typedef unsigned long long ull;

// ---------------- packed f32x2 helpers (Blackwell FFMA2 path) ---------------
__device__ __forceinline__ ull pack2(float lo, float hi) {
    ull r; asm("mov.b64 %0, {%1, %2};" : "=l"(r) : "f"(lo), "f"(hi)); return r;
}
__device__ __forceinline__ ull dup2(float v) {
    ull r; asm("mov.b64 %0, {%1, %1};" : "=l"(r) : "f"(v)); return r;
}
__device__ __forceinline__ void unpack2(ull v, float& lo, float& hi) {
    asm("mov.b64 {%0, %1}, %2;" : "=f"(lo), "=f"(hi) : "l"(v));
}
__device__ __forceinline__ ull fma2(ull a, ull b, ull c) {
    ull d; asm("fma.rn.f32x2 %0, %1, %2, %3;" : "=l"(d) : "l"(a), "l"(b), "l"(c)); return d;
}
__device__ __forceinline__ void cp_async4(unsigned int saddr, const void* gptr, int src_sz) {
    asm volatile("cp.async.ca.shared.global [%0], [%1], 4, %2;"
                 :: "r"(saddr), "l"(gptr), "r"(src_sz));
}
__device__ __forceinline__ void cp_commit() { asm volatile("cp.async.commit_group;"); }
__device__ __forceinline__ void cp_wait0()  { asm volatile("cp.async.wait_group 0;"); }

// ---------------- scratch (static device globals; no allocations) ----------
__device__ float g_cA[96 * 256 * 256];          // 25 MB

// ---------------- Kernel A: Haar DWT (float4 loads, 2 px / thread) ---------
__global__ void dwt_kernel(const float* __restrict__ x, float* __restrict__ out_high) {
    int img = blockIdx.y;
    int t = blockIdx.x * 256 + threadIdx.x;       // 0..32767
    int oy = t >> 7;
    int oxp = (t & 127) << 1;                     // even output col
    const float* base = x + (size_t)img * 262144 + (size_t)oy * 1024 + 2 * oxp;
    float4 tp = *(const float4*)base;
    float4 bt = *(const float4*)(base + 512);
    float cA0 = (tp.x + tp.y + bt.x + bt.y) * 0.5f;
    float cH0 = (tp.x + tp.y - bt.x - bt.y) * 0.5f;
    float cV0 = (tp.x - tp.y + bt.x - bt.y) * 0.5f;
    float cA1 = (tp.z + tp.w + bt.z + bt.w) * 0.5f;
    float cH1 = (tp.z + tp.w - bt.z - bt.w) * 0.5f;
    float cV1 = (tp.z - tp.w + bt.z - bt.w) * 0.5f;
    int o = oy * 256 + oxp;
    *(float2*)(g_cA + (size_t)img * 65536 + o) = make_float2(cA0, cA1);
    float* hb = out_high + (size_t)img * 131072;
    *(float2*)(hb + o) = make_float2(cH0, cH1);
    *(float2*)(hb + 65536 + o) = make_float2(cV0, cV1);
}

// 9-tap accumulate macro (phase 1): packed weight W applied to 2x2 conv pos
#define K9(W, KY, KX)                                   \
    a0 = fma2(pd[(KY)][(KX)],         (W), a0);         \
    a1 = fma2(pd[(KY)][(KX) + 1],     (W), a1);         \
    a2 = fma2(pd[(KY) + 1][(KX)],     (W), a2);         \
    a3 = fma2(pd[(KY) + 1][(KX) + 1], (W), a3);

// phase-2 3-tap row processor: RA feeds conv-row (out pos 0,1), RB (pos 2,3)
#define PROC3(KY, RA, RB)                                                     \
    _Pragma("unroll")                                                         \
    for (int j = 0; j < 4; j++) {                                             \
        const ull* wp = wkp + (((4 * g + j) * 8 + icp) * 3 + (KY)) * 4;       \
        ulonglong2 wab = *(const ulonglong2*)wp;                              \
        ull wc = wp[2];                                                       \
        acc[j][0] = fma2(RA[0], wab.x, acc[j][0]);                            \
        acc[j][1] = fma2(RA[1], wab.x, acc[j][1]);                            \
        acc[j][2] = fma2(RB[0], wab.x, acc[j][2]);                            \
        acc[j][3] = fma2(RB[1], wab.x, acc[j][3]);                            \
        acc[j][0] = fma2(RA[1], wab.y, acc[j][0]);                            \
        acc[j][1] = fma2(RA[2], wab.y, acc[j][1]);                            \
        acc[j][2] = fma2(RB[1], wab.y, acc[j][2]);                            \
        acc[j][3] = fma2(RB[2], wab.y, acc[j][3]);                            \
        acc[j][0] = fma2(RA[2], wc, acc[j][0]);                               \
        acc[j][1] = fma2(RA[3], wc, acc[j][1]);                               \
        acc[j][2] = fma2(RB[2], wc, acc[j][2]);                               \
        acc[j][3] = fma2(RB[3], wc, acc[j][3]);                               \
    }

#define LDROW(DST, OFF)                                                       \
    { ulonglong2 t0 = *(const ulonglong2*)(pp + (OFF));                       \
      ulonglong2 t1 = *(const ulonglong2*)(pp + (OFF) + 2);                   \
      DST[0] = t0.x; DST[1] = t0.y; DST[2] = t1.x; DST[3] = t1.y; }

#define NBLK 296
#define NTILE 1536

// ---------------- Persistent fused kernel -----------------------------------
// grid 296 (2/SM), block 512. Per tile: phase1 conv1+pool -> smem t1 stored as
// 8 channel-PAIR planes (ull per position); phase2 conv2+pool with ic-pair
// lanes (no dup2); conv3. Next tile's cA prefetched via cp.async in phase 2.
__global__ void __launch_bounds__(512, 2)
fused_conv_kernel(const float* __restrict__ w1, const float* __restrict__ b1,
                  const float* __restrict__ w2, const float* __restrict__ b2,
                  const float* __restrict__ w3, const float* __restrict__ b3,
                  float* __restrict__ out_low) {
    extern __shared__ float sm[];
    float* cAt = sm;                       // 70 * 72 = 5040 floats
    ull*   insp = (ull*)(sm + 5040);       // 8 planes * 1224 ull = 19584 floats
    ull*   wkp = insp + 9792;              // 768 ull (1536 fl): (oc,icp,ky,4)
    ull*   w1p = wkp + 768;                // 80 ull (160 fl)
    float* tail = (float*)(w1p + 80);
    float* b1s = tail;                     // 16
    float* b2s = tail + 16;                // 8
    float* w3s = tail + 24;                // 32
    float* b3s = tail + 56;                // 4
    float* v4buf = tail + 64;              // 2048 floats

    int tid = threadIdx.x;                               // 512 threads

    // ---- weights (once per block) ----
    if (tid < 80) {
        int op = tid / 10, k = tid - op * 10;
        w1p[tid] = (k < 9) ? pack2(w1[(2 * op) * 9 + k], w1[(2 * op + 1) * 9 + k]) : 0ull;
    }
    // wkp: (oc, icp, ky, kx[0..3]) -> pair over (2*icp, 2*icp+1)
    for (int i = tid; i < 768; i += 512) {
        int oc = i / 96;
        int rem = i - oc * 96;
        int icp = rem / 12;
        int rem2 = rem - icp * 12;
        int ky = rem2 >> 2, kx = rem2 & 3;
        wkp[i] = (kx < 3) ? pack2(w2[oc * 144 + (2 * icp) * 9 + ky * 3 + kx],
                                  w2[oc * 144 + (2 * icp + 1) * 9 + ky * 3 + kx]) : 0ull;
    }
    if (tid < 16) b1s[tid] = b1[tid];
    if (tid < 8) b2s[tid] = b2[tid];
    if (tid < 32) w3s[tid] = w3[tid];
    if (tid < 4) b3s[tid] = b3[tid];

    unsigned int cAt_s = (unsigned int)__cvta_generic_to_shared(cAt);

    // initial prefetch for first tile
    {
        int tile0 = blockIdx.x;
        int img = tile0 >> 4;
        int tt = tile0 & 15;
        int by0 = (tt >> 2) * 32, bx0 = (tt & 3) * 32;
        const float* in = g_cA + (size_t)img * 65536;
        int cy0 = 2 * by0 - 3, cx0 = 2 * bx0 - 3;
        for (int idx = tid; idx < 70 * 70; idx += 512) {
            int r = idx / 70, c = idx - r * 70;
            int gy = cy0 + r, gx = cx0 + c;
            bool ok = ((unsigned)gy < 256u) && ((unsigned)gx < 256u);
            const float* src = ok ? (in + gy * 256 + gx) : in;
            cp_async4(cAt_s + (unsigned int)(r * 72 + c) * 4u, src, ok ? 4 : 0);
        }
        cp_commit();
    }

    for (int tile = blockIdx.x; tile < NTILE; tile += NBLK) {
        int img = tile >> 4;
        int tt = tile & 15;
        int by0 = (tt >> 2) * 32, bx0 = (tt & 3) * 32;

        cp_wait0();
        __syncthreads();                   // cAt ready, prior-tile v4buf free

        // ---- phase 1: t1 tile (34x34 positions x 8 channel-pair planes) ----
        for (int pos = tid; pos < 34 * 34; pos += 512) {
            int r = pos / 34, c = pos - r * 34;
            int ty = by0 - 1 + r, tx = bx0 - 1 + c;       // global t1 coords
            ull* op_out = insp + r * 36 + c;
            if ((unsigned)ty < 128u && (unsigned)tx < 128u) {
                const float* ip = cAt + 2 * r * 72 + 2 * c;
                ull pd[4][4];
#pragma unroll
                for (int rr = 0; rr < 4; rr++) {
                    float2 u0 = *(const float2*)(ip + rr * 72);
                    float2 u1 = *(const float2*)(ip + rr * 72 + 2);
                    pd[rr][0] = dup2(u0.x); pd[rr][1] = dup2(u0.y);
                    pd[rr][2] = dup2(u1.x); pd[rr][3] = dup2(u1.y);
                }
#pragma unroll
                for (int op = 0; op < 8; op++) {
                    ull bb = pack2(b1s[2 * op], b1s[2 * op + 1]);
                    ull a0 = bb, a1 = bb, a2 = bb, a3 = bb;
                    const ull* wp = w1p + op * 10;
                    ulonglong2 w01 = *(const ulonglong2*)wp;
                    ulonglong2 w23 = *(const ulonglong2*)(wp + 2);
                    ulonglong2 w45 = *(const ulonglong2*)(wp + 4);
                    ulonglong2 w67 = *(const ulonglong2*)(wp + 6);
                    ull w8 = wp[8];
                    K9(w01.x, 0, 0) K9(w01.y, 0, 1) K9(w23.x, 0, 2)
                    K9(w23.y, 1, 0) K9(w45.x, 1, 1) K9(w45.y, 1, 2)
                    K9(w67.x, 2, 0) K9(w67.y, 2, 1) K9(w8,    2, 2)
                    float s0l, s0h, s1l, s1h, s2l, s2h, s3l, s3h;
                    unpack2(a0, s0l, s0h); unpack2(a1, s1l, s1h);
                    unpack2(a2, s2l, s2h); unpack2(a3, s3l, s3h);
                    float ml = fmaxf(fmaxf(s0l, s1l), fmaxf(s2l, s3l));
                    float mh = fmaxf(fmaxf(s0h, s1h), fmaxf(s2h, s3h));
                    op_out[op * 1224] = pack2(fmaxf(ml, 0.f), fmaxf(mh, 0.f));
                }
            } else {
#pragma unroll
                for (int icp = 0; icp < 8; icp++) op_out[icp * 1224] = 0ull;
            }
        }
        __syncthreads();                   // insp ready, cAt dead

        // ---- prefetch next tile's cA halo into cAt (overlaps phase 2) ----
        {
            int nt = tile + NBLK;
            if (nt < NTILE) {
                int nimg = nt >> 4;
                int ntt = nt & 15;
                int nby = (ntt >> 2) * 32, nbx = (ntt & 3) * 32;
                const float* nin = g_cA + (size_t)nimg * 65536;
                int cy0 = 2 * nby - 3, cx0 = 2 * nbx - 3;
                for (int idx = tid; idx < 70 * 70; idx += 512) {
                    int r = idx / 70, c = idx - r * 70;
                    int gy = cy0 + r, gx = cx0 + c;
                    bool ok = ((unsigned)gy < 256u) && ((unsigned)gx < 256u);
                    const float* src = ok ? (nin + gy * 256 + gx) : nin;
                    cp_async4(cAt_s + (unsigned int)(r * 72 + c) * 4u, src, ok ? 4 : 0);
                }
            }
            cp_commit();
        }

        // ---- phase 2: conv2 + relu + pool, ic-pair lanes (no dup2) ----
        int pix = tid & 255, g = tid >> 8;           // g: ocs 4g..4g+3
        int tyx = pix & 15, tyy = pix >> 4;
        int ly = 2 * tyy, lx = 2 * tyx;
        ull acc[4][4];
#pragma unroll
        for (int j = 0; j < 4; j++) {
            ull bb = pack2(b2s[4 * g + j], 0.f);
            acc[j][0] = bb; acc[j][1] = bb; acc[j][2] = bb; acc[j][3] = bb;
        }

#pragma unroll 1
        for (int icp = 0; icp < 8; icp++) {
            const ull* pp = insp + icp * 1224 + ly * 36 + lx;
            ull ra[4], rb[4];
            LDROW(ra, 0)
            LDROW(rb, 36)
            PROC3(0, ra, rb)
            LDROW(ra, 72)
            PROC3(1, rb, ra)
            LDROW(rb, 108)
            PROC3(2, ra, rb)
        }

        float v4[4];
#pragma unroll
        for (int j = 0; j < 4; j++) {
            float s0l, s0h, s1l, s1h, s2l, s2h, s3l, s3h;
            unpack2(acc[j][0], s0l, s0h); unpack2(acc[j][1], s1l, s1h);
            unpack2(acc[j][2], s2l, s2h); unpack2(acc[j][3], s3l, s3h);
            float s0 = s0l + s0h, s1 = s1l + s1h, s2 = s2l + s2h, s3 = s3l + s3h;
            float m = fmaxf(fmaxf(s0, s1), fmaxf(s2, s3));
            v4[j] = fmaxf(m, 0.f);
        }
        *(float4*)(v4buf + pix * 8 + 4 * g) = make_float4(v4[0], v4[1], v4[2], v4[3]);
        __syncthreads();

        // ---- conv3 (8->4, 1x1): 512 threads, 2 outputs each ----
        {
            int p = tid >> 1;                    // pixel 0..255
            int half = (tid & 1) * 2;            // o3 in {half, half+1}
            float4 lo4 = *(const float4*)(v4buf + p * 8);
            float4 hi4 = *(const float4*)(v4buf + p * 8 + 4);
            float v8[8] = {lo4.x, lo4.y, lo4.z, lo4.w, hi4.x, hi4.y, hi4.z, hi4.w};
            int oy = (by0 >> 1) + (p >> 4);
            int ox = (bx0 >> 1) + (p & 15);
            float* ob = out_low + (size_t)img * 4 * 4096 + oy * 64 + ox;
#pragma unroll
            for (int j = 0; j < 2; j++) {
                int o3 = half + j;
                float s = b3s[o3];
#pragma unroll
                for (int ic = 0; ic < 8; ic++) s += v8[ic] * w3s[o3 * 8 + ic];
                ob[o3 * 4096] = s;
            }
        }
    }
}

// ---------------------------------------------------------------------------
extern "C" void kernel_launch(void* const* d_in, const int* in_sizes, int n_in,
                              void* d_out, int out_size) {
    const float* x  = (const float*)d_in[0];
    const float* w1 = (const float*)d_in[1];
    const float* b1 = (const float*)d_in[2];
    const float* w2 = (const float*)d_in[3];
    const float* b2 = (const float*)d_in[4];
    const float* w3 = (const float*)d_in[5];
    const float* b3 = (const float*)d_in[6];
    float* out = (float*)d_out;

    const int LOW_SIZE = 96 * 4 * 64 * 64;                               // 1,572,864
    const int SMEM_F = (5040 + 19584 + 1536 + 160 + 64 + 2048) * 4;      // 113,728 B

    cudaFuncSetAttribute(fused_conv_kernel, cudaFuncAttributeMaxDynamicSharedMemorySize, SMEM_F);

    dwt_kernel<<<dim3(128, 96), 256>>>(x, out + LOW_SIZE);
    fused_conv_kernel<<<NBLK, 512, SMEM_F>>>(w1, b1, w2, b2, w3, b3, out);
}

// round 9
// speedup vs baseline: 1.0664x; 1.0664x over previous
#include <cuda_runtime.h>
#include <cstdint>

typedef unsigned long long ull;

// ---------------- packed f32x2 helpers (Blackwell FFMA2 path) ---------------
__device__ __forceinline__ ull pack2(float lo, float hi) {
    ull r; asm("mov.b64 %0, {%1, %2};" : "=l"(r) : "f"(lo), "f"(hi)); return r;
}
__device__ __forceinline__ ull dup2(float v) {
    ull r; asm("mov.b64 %0, {%1, %1};" : "=l"(r) : "f"(v)); return r;
}
__device__ __forceinline__ void unpack2(ull v, float& lo, float& hi) {
    asm("mov.b64 {%0, %1}, %2;" : "=f"(lo), "=f"(hi) : "l"(v));
}
__device__ __forceinline__ ull fma2(ull a, ull b, ull c) {
    ull d; asm("fma.rn.f32x2 %0, %1, %2, %3;" : "=l"(d) : "l"(a), "l"(b), "l"(c)); return d;
}
__device__ __forceinline__ void cp_async4(unsigned int saddr, const void* gptr, int src_sz) {
    asm volatile("cp.async.ca.shared.global [%0], [%1], 4, %2;"
                 :: "r"(saddr), "l"(gptr), "r"(src_sz));
}
__device__ __forceinline__ void cp_commit() { asm volatile("cp.async.commit_group;"); }
__device__ __forceinline__ void cp_wait0()  { asm volatile("cp.async.wait_group 0;"); }

// ---------------- scratch (static device globals; no allocations) ----------
__device__ float g_cA[96 * 256 * 256];          // 25 MB

// ---------------- Kernel A: Haar DWT (float4 loads, 2 px / thread) ---------
__global__ void dwt_kernel(const float* __restrict__ x, float* __restrict__ out_high) {
    int img = blockIdx.y;
    int t = blockIdx.x * 256 + threadIdx.x;       // 0..32767
    int oy = t >> 7;
    int oxp = (t & 127) << 1;                     // even output col
    const float* base = x + (size_t)img * 262144 + (size_t)oy * 1024 + 2 * oxp;
    float4 tp = *(const float4*)base;
    float4 bt = *(const float4*)(base + 512);
    float cA0 = (tp.x + tp.y + bt.x + bt.y) * 0.5f;
    float cH0 = (tp.x + tp.y - bt.x - bt.y) * 0.5f;
    float cV0 = (tp.x - tp.y + bt.x - bt.y) * 0.5f;
    float cA1 = (tp.z + tp.w + bt.z + bt.w) * 0.5f;
    float cH1 = (tp.z + tp.w - bt.z - bt.w) * 0.5f;
    float cV1 = (tp.z - tp.w + bt.z - bt.w) * 0.5f;
    int o = oy * 256 + oxp;
    *(float2*)(g_cA + (size_t)img * 65536 + o) = make_float2(cA0, cA1);
    float* hb = out_high + (size_t)img * 131072;
    *(float2*)(hb + o) = make_float2(cH0, cH1);
    *(float2*)(hb + 65536 + o) = make_float2(cV0, cV1);
}

// 9-tap accumulate macro: packed weight W applied to 2x2 conv positions
#define K9(W, KY, KX)                                   \
    a0 = fma2(pd[(KY)][(KX)],         (W), a0);         \
    a1 = fma2(pd[(KY)][(KX) + 1],     (W), a1);         \
    a2 = fma2(pd[(KY) + 1][(KX)],     (W), a2);         \
    a3 = fma2(pd[(KY) + 1][(KX) + 1], (W), a3);

#define NBLK 296
#define NTILE 1536

// ---------------- Persistent fused kernel -----------------------------------
// grid 296 (2/SM), block 512. Per tile: phase1 conv1+pool -> smem t1, work
// units = (position, op-half) for tail balance; phase2 conv2+pool (op-pair
// split); conv3. Next tile's cA prefetched via cp.async during phase 2.
__global__ void __launch_bounds__(512, 2)
fused_conv_kernel(const float* __restrict__ w1, const float* __restrict__ b1,
                  const float* __restrict__ w2, const float* __restrict__ b2,
                  const float* __restrict__ w3, const float* __restrict__ b3,
                  float* __restrict__ out_low) {
    extern __shared__ float sm[];
    float* cAt = sm;                       // 70 * 72 = 5040 floats
    float* ins = sm + 5040;                // 16 * 34 * 36 = 19584 floats
    ull*   w2p = (ull*)(ins + 19584);      // 640 ull
    ull*   w1p = w2p + 640;                // 80 ull
    float* tail = (float*)(w1p + 80);
    float* b1s = tail;                     // 16
    float* b2s = tail + 16;                // 8
    float* w3s = tail + 24;                // 32
    float* b3s = tail + 56;                // 4
    float* v4buf = tail + 64;              // 2048 floats

    int tid = threadIdx.x;                               // 512 threads

    // ---- weights (once per block) ----
    if (tid < 80) {
        int op = tid / 10, k = tid - op * 10;
        w1p[tid] = (k < 9) ? pack2(w1[(2 * op) * 9 + k], w1[(2 * op + 1) * 9 + k]) : 0ull;
    }
    for (int i = tid; i < 640; i += 512) {
        int op = i / 160;
        int rem = i - op * 160;            // ic*10 + k
        int ic = rem / 10, k = rem - ic * 10;
        w2p[i] = (k < 9) ? pack2(w2[(2 * op) * 144 + ic * 9 + k],
                                 w2[(2 * op + 1) * 144 + ic * 9 + k]) : 0ull;
    }
    if (tid < 16) b1s[tid] = b1[tid];
    if (tid < 8) b2s[tid] = b2[tid];
    if (tid < 32) w3s[tid] = w3[tid];
    if (tid < 4) b3s[tid] = b3[tid];

    unsigned int cAt_s = (unsigned int)__cvta_generic_to_shared(cAt);

    // initial prefetch for first tile
    {
        int tile0 = blockIdx.x;
        int img = tile0 >> 4;
        int tt = tile0 & 15;
        int by0 = (tt >> 2) * 32, bx0 = (tt & 3) * 32;
        const float* in = g_cA + (size_t)img * 65536;
        int cy0 = 2 * by0 - 3, cx0 = 2 * bx0 - 3;
        for (int idx = tid; idx < 70 * 70; idx += 512) {
            int r = idx / 70, c = idx - r * 70;
            int gy = cy0 + r, gx = cx0 + c;
            bool ok = ((unsigned)gy < 256u) && ((unsigned)gx < 256u);
            const float* src = ok ? (in + gy * 256 + gx) : in;
            cp_async4(cAt_s + (unsigned int)(r * 72 + c) * 4u, src, ok ? 4 : 0);
        }
        cp_commit();
    }

    for (int tile = blockIdx.x; tile < NTILE; tile += NBLK) {
        int img = tile >> 4;
        int tt = tile & 15;
        int by0 = (tt >> 2) * 32, bx0 = (tt & 3) * 32;

        cp_wait0();
        __syncthreads();                   // cAt ready, prior-tile v4buf free

        // ---- phase 1: units = (position, op-half); 2312 units ----
        for (int u = tid; u < 2 * 34 * 34; u += 512) {
            int pos = u >> 1, h = u & 1;               // h: ops 4h..4h+3
            int r = pos / 34, c = pos - r * 34;
            int ty = by0 - 1 + r, tx = bx0 - 1 + c;    // global t1 coords
            float* op_out = ins + (8 * h) * 1224 + r * 36 + c;
            if ((unsigned)ty < 128u && (unsigned)tx < 128u) {
                const float* ip = cAt + 2 * r * 72 + 2 * c;
                ull pd[4][4];
#pragma unroll
                for (int rr = 0; rr < 4; rr++) {
                    float2 u0 = *(const float2*)(ip + rr * 72);
                    float2 u1 = *(const float2*)(ip + rr * 72 + 2);
                    pd[rr][0] = dup2(u0.x); pd[rr][1] = dup2(u0.y);
                    pd[rr][2] = dup2(u1.x); pd[rr][3] = dup2(u1.y);
                }
#pragma unroll
                for (int oq = 0; oq < 4; oq++) {
                    int op = 4 * h + oq;
                    ull bb = pack2(b1s[2 * op], b1s[2 * op + 1]);
                    ull a0 = bb, a1 = bb, a2 = bb, a3 = bb;
                    const ull* wp = w1p + op * 10;
                    ulonglong2 w01 = *(const ulonglong2*)wp;
                    ulonglong2 w23 = *(const ulonglong2*)(wp + 2);
                    ulonglong2 w45 = *(const ulonglong2*)(wp + 4);
                    ulonglong2 w67 = *(const ulonglong2*)(wp + 6);
                    ull w8 = wp[8];
                    K9(w01.x, 0, 0) K9(w01.y, 0, 1) K9(w23.x, 0, 2)
                    K9(w23.y, 1, 0) K9(w45.x, 1, 1) K9(w45.y, 1, 2)
                    K9(w67.x, 2, 0) K9(w67.y, 2, 1) K9(w8,    2, 2)
                    float s0l, s0h, s1l, s1h, s2l, s2h, s3l, s3h;
                    unpack2(a0, s0l, s0h); unpack2(a1, s1l, s1h);
                    unpack2(a2, s2l, s2h); unpack2(a3, s3l, s3h);
                    float ml = fmaxf(fmaxf(s0l, s1l), fmaxf(s2l, s3l));
                    float mh = fmaxf(fmaxf(s0h, s1h), fmaxf(s2h, s3h));
                    op_out[(2 * oq) * 1224]     = fmaxf(ml, 0.f);
                    op_out[(2 * oq + 1) * 1224] = fmaxf(mh, 0.f);
                }
            } else {
#pragma unroll
                for (int q = 0; q < 8; q++) op_out[q * 1224] = 0.f;
            }
        }
        __syncthreads();                   // ins ready, cAt dead

        // ---- prefetch next tile's cA halo into cAt (overlaps phase 2) ----
        {
            int nt = tile + NBLK;
            if (nt < NTILE) {
                int nimg = nt >> 4;
                int ntt = nt & 15;
                int nby = (ntt >> 2) * 32, nbx = (ntt & 3) * 32;
                const float* nin = g_cA + (size_t)nimg * 65536;
                int cy0 = 2 * nby - 3, cx0 = 2 * nbx - 3;
                for (int idx = tid; idx < 70 * 70; idx += 512) {
                    int r = idx / 70, c = idx - r * 70;
                    int gy = cy0 + r, gx = cx0 + c;
                    bool ok = ((unsigned)gy < 256u) && ((unsigned)gx < 256u);
                    const float* src = ok ? (nin + gy * 256 + gx) : nin;
                    cp_async4(cAt_s + (unsigned int)(r * 72 + c) * 4u, src, ok ? 4 : 0);
                }
            }
            cp_commit();
        }

        // ---- phase 2: conv2 + relu + pool (oc split across 2 groups) ----
        int pix = tid & 255, g = tid >> 8;
        int tyx = pix & 15, tyy = pix >> 4;
        int ly = 2 * tyy, lx = 2 * tyx;
        ull acc[2][4];
#pragma unroll
        for (int op2 = 0; op2 < 2; op2++) {
            int op = 2 * g + op2;
            ull bb = pack2(b2s[2 * op], b2s[2 * op + 1]);
            acc[op2][0] = bb; acc[op2][1] = bb; acc[op2][2] = bb; acc[op2][3] = bb;
        }

#pragma unroll 1
        for (int ic = 0; ic < 16; ic++) {
            const float* ip = ins + ic * 1224 + ly * 36 + lx;
            ull pd[4][4];
#pragma unroll
            for (int rr = 0; rr < 4; rr++) {
                float2 u0 = *(const float2*)(ip + rr * 36);
                float2 u1 = *(const float2*)(ip + rr * 36 + 2);
                pd[rr][0] = dup2(u0.x); pd[rr][1] = dup2(u0.y);
                pd[rr][2] = dup2(u1.x); pd[rr][3] = dup2(u1.y);
            }
#pragma unroll
            for (int op2 = 0; op2 < 2; op2++) {
                int op = 2 * g + op2;
                const ull* wp = w2p + (op * 16 + ic) * 10;
                ulonglong2 w01 = *(const ulonglong2*)wp;
                ulonglong2 w23 = *(const ulonglong2*)(wp + 2);
                ulonglong2 w45 = *(const ulonglong2*)(wp + 4);
                ulonglong2 w67 = *(const ulonglong2*)(wp + 6);
                ull w8 = wp[8];
                ull a0 = acc[op2][0], a1 = acc[op2][1], a2 = acc[op2][2], a3 = acc[op2][3];
                K9(w01.x, 0, 0) K9(w01.y, 0, 1) K9(w23.x, 0, 2)
                K9(w23.y, 1, 0) K9(w45.x, 1, 1) K9(w45.y, 1, 2)
                K9(w67.x, 2, 0) K9(w67.y, 2, 1) K9(w8,    2, 2)
                acc[op2][0] = a0; acc[op2][1] = a1; acc[op2][2] = a2; acc[op2][3] = a3;
            }
        }

        float v4[4];
#pragma unroll
        for (int op2 = 0; op2 < 2; op2++) {
            float s0l, s0h, s1l, s1h, s2l, s2h, s3l, s3h;
            unpack2(acc[op2][0], s0l, s0h); unpack2(acc[op2][1], s1l, s1h);
            unpack2(acc[op2][2], s2l, s2h); unpack2(acc[op2][3], s3l, s3h);
            float ml = fmaxf(fmaxf(s0l, s1l), fmaxf(s2l, s3l));
            float mh = fmaxf(fmaxf(s0h, s1h), fmaxf(s2h, s3h));
            v4[2 * op2]     = fmaxf(ml, 0.f);
            v4[2 * op2 + 1] = fmaxf(mh, 0.f);
        }
        *(float4*)(v4buf + pix * 8 + 4 * g) = make_float4(v4[0], v4[1], v4[2], v4[3]);
        __syncthreads();

        // ---- conv3 (8->4, 1x1): 512 threads, 2 outputs each ----
        {
            int p = tid >> 1;                    // pixel 0..255
            int half = (tid & 1) * 2;            // o3 in {half, half+1}
            float4 lo4 = *(const float4*)(v4buf + p * 8);
            float4 hi4 = *(const float4*)(v4buf + p * 8 + 4);
            float v8[8] = {lo4.x, lo4.y, lo4.z, lo4.w, hi4.x, hi4.y, hi4.z, hi4.w};
            int oy = (by0 >> 1) + (p >> 4);
            int ox = (bx0 >> 1) + (p & 15);
            float* ob = out_low + (size_t)img * 4 * 4096 + oy * 64 + ox;
#pragma unroll
            for (int j = 0; j < 2; j++) {
                int o3 = half + j;
                float s = b3s[o3];
#pragma unroll
                for (int ic = 0; ic < 8; ic++) s += v8[ic] * w3s[o3 * 8 + ic];
                ob[o3 * 4096] = s;
            }
        }
    }
}

// ---------------------------------------------------------------------------
extern "C" void kernel_launch(void* const* d_in, const int* in_sizes, int n_in,
                              void* d_out, int out_size) {
    const float* x  = (const float*)d_in[0];
    const float* w1 = (const float*)d_in[1];
    const float* b1 = (const float*)d_in[2];
    const float* w2 = (const float*)d_in[3];
    const float* b2 = (const float*)d_in[4];
    const float* w3 = (const float*)d_in[5];
    const float* b3 = (const float*)d_in[6];
    float* out = (float*)d_out;

    const int LOW_SIZE = 96 * 4 * 64 * 64;                               // 1,572,864
    const int SMEM_F = (5040 + 19584 + 1280 + 160 + 64 + 2048) * 4;      // 112,704 B

    cudaFuncSetAttribute(fused_conv_kernel, cudaFuncAttributeMaxDynamicSharedMemorySize, SMEM_F);

    dwt_kernel<<<dim3(128, 96), 256>>>(x, out + LOW_SIZE);
    fused_conv_kernel<<<NBLK, 512, SMEM_F>>>(w1, b1, w2, b2, w3, b3, out);
}